// round 4
// baseline (speedup 1.0000x reference)
#include <cuda_runtime.h>
#include <cuda_bf16.h>
#include <math.h>
#include <stdint.h>

// ---------------------------------------------------------------------------
// AttentiveFPConv: out = tanh(x@Wn + bn + aggr@Wg + bg)
//   aggr[u] = sum_{e: row[e]==u} g[col[e]],  g[v] = x[v] * sigmoid((x@Wa+ba)[v])
// N = 40000, E = 640000, D = 128.
// GEMMs: mma.sync m16n8k16 bf16, 2-way hi/lo split (3 terms) for fp32 accuracy.
// (tcgen05 unavailable: harness targets sm_100 without the 'a' feature set.)
// ---------------------------------------------------------------------------

#define NODES_MAX 40000
#define EDGES_MAX 640000
#define DIM 128

__device__ float g_yn[NODES_MAX * DIM];
__device__ float g_ga[NODES_MAX * DIM];
__device__ float g_aggr[NODES_MAX * DIM];
__device__ int2  g_eidx[EDGES_MAX];
__device__ int   g_is64;
// Weights pre-transposed to [n][k], split hi/lo bf16: [matrix][hi/lo][n*128+k]
__device__ __align__(16) __nv_bfloat16 g_wconv[3][2][DIM * DIM];

// ---------------------------------------------------------------------------
__device__ __forceinline__ uint32_t smem_u32(const void* p) {
    uint32_t a;
    asm("{ .reg .u64 t; cvta.to.shared.u64 t, %1; cvt.u32.u64 %0, t; }" : "=r"(a) : "l"(p));
    return a;
}

__device__ __forceinline__ void ldsm4(uint32_t a, uint32_t& r0, uint32_t& r1,
                                      uint32_t& r2, uint32_t& r3) {
    asm volatile("ldmatrix.sync.aligned.m8n8.x4.shared.b16 {%0,%1,%2,%3}, [%4];"
                 : "=r"(r0), "=r"(r1), "=r"(r2), "=r"(r3) : "r"(a));
}

__device__ __forceinline__ void mma16816(float* c, uint32_t a0, uint32_t a1,
                                         uint32_t a2, uint32_t a3,
                                         uint32_t b0, uint32_t b1) {
    asm volatile(
        "mma.sync.aligned.m16n8k16.row.col.f32.bf16.bf16.f32 "
        "{%0,%1,%2,%3}, {%4,%5,%6,%7}, {%8,%9}, {%0,%1,%2,%3};"
        : "+f"(c[0]), "+f"(c[1]), "+f"(c[2]), "+f"(c[3])
        : "r"(a0), "r"(a1), "r"(a2), "r"(a3), "r"(b0), "r"(b1));
}

__device__ __forceinline__ uint32_t pack_bf16x2(float x, float y) {
    __nv_bfloat16 hx = __float2bfloat16(x), hy = __float2bfloat16(y);
    return (uint32_t)*(unsigned short*)&hx | ((uint32_t)*(unsigned short*)&hy << 16);
}

// ---------------------------------------------------------------------------
__global__ void zero_aggr_kernel(int total_f4) {
    int i = blockIdx.x * blockDim.x + threadIdx.x;
    if (i < total_f4)
        ((float4*)g_aggr)[i] = make_float4(0.f, 0.f, 0.f, 0.f);
}

__global__ void detect_idx_kernel(const int* __restrict__ ei32) {
    if (threadIdx.x == 0 && blockIdx.x == 0) {
        int is64 = 1;
        #pragma unroll
        for (int i = 0; i < 32; i++)
            if (ei32[2 * i + 1] != 0) { is64 = 0; break; }
        g_is64 = is64;
    }
}

__global__ __launch_bounds__(256) void pack_idx_kernel(const void* __restrict__ ei, int E) {
    int e = blockIdx.x * blockDim.x + threadIdx.x;
    if (e >= E) return;
    int row, col;
    if (g_is64) {
        const long long* p = (const long long*)ei;
        row = (int)p[e]; col = (int)p[E + e];
    } else {
        const int* p = (const int*)ei;
        row = p[e]; col = p[E + e];
    }
    g_eidx[e] = make_int2(row, col);
}

// W[k][n] -> Bt[n][k] hi/lo bf16 (plain row-major, stride 128).
__global__ __launch_bounds__(256) void prep_weights_kernel(
    const float* __restrict__ Wn, const float* __restrict__ Wg,
    const float* __restrict__ Wa)
{
    const float* W = blockIdx.x == 0 ? Wn : (blockIdx.x == 1 ? Wg : Wa);
    uint32_t* hi = (uint32_t*)g_wconv[blockIdx.x][0];
    uint32_t* lo = (uint32_t*)g_wconv[blockIdx.x][1];
    for (int i = threadIdx.x; i < DIM * DIM / 2; i += blockDim.x) {
        int n = i >> 6;
        int k = (i & 63) * 2;
        float v0 = W[(size_t)k * DIM + n];
        float v1 = W[(size_t)(k + 1) * DIM + n];
        float h0 = __bfloat162float(__float2bfloat16(v0));
        float h1 = __bfloat162float(__float2bfloat16(v1));
        hi[(n * DIM + k) >> 1] = pack_bf16x2(h0, h1);
        lo[(n * DIM + k) >> 1] = pack_bf16x2(v0 - h0, v1 - h1);
    }
}

// ---------------------------------------------------------------------------
// mma.sync GEMM: out[m][n] = epilogue(sum_k A[m][k]*W[k][n] + bias[n])
//   mode 0: +bias; mode 1: extra*sigmoid(acc+bias); mode 2: tanh(acc+bias+extra)
// CTA: 128x128 tile, 256 thr, warp grid 4(M)x2(N), warp tile 32x64, K resident.
// SMEM rows padded to 272B (136 bf16) for conflict-free ldmatrix.
// ---------------------------------------------------------------------------
#define ASTRIDE 272
#define BUF_SZ  (DIM * ASTRIDE)       // 34816
#define SM_TOTAL (4 * BUF_SZ)         // 139264

__global__ __launch_bounds__(256) void gemm_mma_fused(
    const float* __restrict__ A, int widx,
    const float* __restrict__ bias, const float* __restrict__ extra,
    float* __restrict__ out, int N, int mode)
{
    extern __shared__ __align__(16) char smem[];
    const uint32_t sb  = smem_u32(smem);
    const uint32_t sAH = sb, sAL = sb + BUF_SZ, sBH = sb + 2 * BUF_SZ, sBL = sb + 3 * BUF_SZ;
    const int tid = threadIdx.x, lane = tid & 31, wid = tid >> 5;
    const int m0 = blockIdx.x * 128;

    // --- A: load fp32, split hi/lo bf16 into padded SMEM ---
    for (int i = tid; i < 128 * 32; i += 256) {
        int rl = i >> 5;            // local row
        int c4 = (i & 31) * 4;      // k offset
        int r = m0 + rl; if (r >= N) r = N - 1;
        float4 v = *(const float4*)(A + (size_t)r * DIM + c4);
        float h0 = __bfloat162float(__float2bfloat16(v.x));
        float h1 = __bfloat162float(__float2bfloat16(v.y));
        float h2 = __bfloat162float(__float2bfloat16(v.z));
        float h3 = __bfloat162float(__float2bfloat16(v.w));
        uint2 hv = make_uint2(pack_bf16x2(h0, h1), pack_bf16x2(h2, h3));
        uint2 lv = make_uint2(pack_bf16x2(v.x - h0, v.y - h1),
                              pack_bf16x2(v.z - h2, v.w - h3));
        int off = rl * ASTRIDE + c4 * 2;
        *(uint2*)(smem + off)          = hv;
        *(uint2*)(smem + BUF_SZ + off) = lv;
    }
    // --- B: copy pre-split Bt[n][k] into padded SMEM ---
    {
        const uint4* wh = (const uint4*)g_wconv[widx][0];
        const uint4* wl = (const uint4*)g_wconv[widx][1];
        for (int i = tid; i < 2048; i += 256) {
            int r = i >> 4, c = (i & 15) * 16;      // 16B chunks
            int off = r * ASTRIDE + c;
            *(uint4*)(smem + 2 * BUF_SZ + off) = wh[i];
            *(uint4*)(smem + 3 * BUF_SZ + off) = wl[i];
        }
    }
    __syncthreads();

    const int wm = wid & 3;   // M warp (0..3), 32 rows each
    const int wn = wid >> 2;  // N warp (0..1), 64 cols each

    float acc[2][8][4];
    #pragma unroll
    for (int mt = 0; mt < 2; mt++)
        #pragma unroll
        for (int nt = 0; nt < 8; nt++)
            #pragma unroll
            for (int q = 0; q < 4; q++) acc[mt][nt][q] = 0.f;

    for (int s = 0; s < 8; s++) {
        const int k0 = s * 16;
        uint32_t ah[2][4], al[2][4];
        #pragma unroll
        for (int mt = 0; mt < 2; mt++) {
            int row = wm * 32 + mt * 16 + (lane & 15);
            int col = k0 + (lane >> 4) * 8;
            uint32_t off = row * ASTRIDE + col * 2;
            ldsm4(sAH + off, ah[mt][0], ah[mt][1], ah[mt][2], ah[mt][3]);
            ldsm4(sAL + off, al[mt][0], al[mt][1], al[mt][2], al[mt][3]);
        }
        uint32_t bh[8][2], bl[8][2];
        #pragma unroll
        for (int np = 0; np < 4; np++) {
            int g = lane >> 3;
            int row = wn * 64 + np * 16 + (g >> 1) * 8 + (lane & 7);
            int col = k0 + (g & 1) * 8;
            uint32_t off = row * ASTRIDE + col * 2;
            ldsm4(sBH + off, bh[2*np][0], bh[2*np][1], bh[2*np+1][0], bh[2*np+1][1]);
            ldsm4(sBL + off, bl[2*np][0], bl[2*np][1], bl[2*np+1][0], bl[2*np+1][1]);
        }
        #pragma unroll
        for (int mt = 0; mt < 2; mt++)
            #pragma unroll
            for (int nt = 0; nt < 8; nt++) {
                mma16816(acc[mt][nt], ah[mt][0], ah[mt][1], ah[mt][2], ah[mt][3],
                         bh[nt][0], bh[nt][1]);
                mma16816(acc[mt][nt], ah[mt][0], ah[mt][1], ah[mt][2], ah[mt][3],
                         bl[nt][0], bl[nt][1]);
                mma16816(acc[mt][nt], al[mt][0], al[mt][1], al[mt][2], al[mt][3],
                         bh[nt][0], bh[nt][1]);
            }
    }

    // --- Epilogue ---
    float2 bb[8];
    #pragma unroll
    for (int nt = 0; nt < 8; nt++) {
        int n = wn * 64 + nt * 8 + 2 * (lane & 3);
        bb[nt] = *(const float2*)(bias + n);
    }
    #pragma unroll
    for (int mt = 0; mt < 2; mt++) {
        #pragma unroll
        for (int half = 0; half < 2; half++) {
            int m = m0 + wm * 32 + mt * 16 + (lane >> 2) + half * 8;
            if (m >= N) continue;
            #pragma unroll
            for (int nt = 0; nt < 8; nt++) {
                int n = wn * 64 + nt * 8 + 2 * (lane & 3);
                float rx = acc[mt][nt][half * 2 + 0] + bb[nt].x;
                float ry = acc[mt][nt][half * 2 + 1] + bb[nt].y;
                if (mode == 1) {
                    float2 xv = *(const float2*)(extra + (size_t)m * DIM + n);
                    rx = xv.x * (1.f / (1.f + expf(-rx)));
                    ry = xv.y * (1.f / (1.f + expf(-ry)));
                } else if (mode == 2) {
                    float2 yv = *(const float2*)(extra + (size_t)m * DIM + n);
                    rx = tanhf(rx + yv.x);
                    ry = tanhf(ry + yv.y);
                }
                *(float2*)(out + (size_t)m * DIM + n) = make_float2(rx, ry);
            }
        }
    }
}

// ---------------------------------------------------------------------------
// Edge scatter: one warp per edge, red.global.add.v4.f32 per lane.
// ---------------------------------------------------------------------------
__global__ __launch_bounds__(256) void edge_scatter_kernel(int E)
{
    int warp = (int)((blockIdx.x * 256 + threadIdx.x) >> 5);
    if (warp >= E) return;
    int lane = threadIdx.x & 31;

    int2 rc = g_eidx[warp];
    const float* src = g_ga + (size_t)rc.y * DIM + lane * 4;
    float* dst       = g_aggr + (size_t)rc.x * DIM + lane * 4;

    float4 v = *(const float4*)src;
    asm volatile("red.global.add.v4.f32 [%0], {%1, %2, %3, %4};"
                 :: "l"(dst), "f"(v.x), "f"(v.y), "f"(v.z), "f"(v.w)
                 : "memory");
}

// ---------------------------------------------------------------------------
extern "C" void kernel_launch(void* const* d_in, const int* in_sizes, int n_in,
                              void* d_out, int out_size)
{
    const float* x    = (const float*)d_in[0];
    const void*  ei   = d_in[1];
    const float* Wn_w = (const float*)d_in[2];
    const float* Wn_b = (const float*)d_in[3];
    const float* Wg_w = (const float*)d_in[4];
    const float* Wg_b = (const float*)d_in[5];
    const float* Wa_w = (const float*)d_in[6];
    const float* Wa_b = (const float*)d_in[7];
    float* out = (float*)d_out;

    const int N = in_sizes[0] / DIM;
    const int E = in_sizes[1] / 2;

    float *p_yn, *p_ga, *p_aggr;
    cudaGetSymbolAddress((void**)&p_yn,   g_yn);
    cudaGetSymbolAddress((void**)&p_ga,   g_ga);
    cudaGetSymbolAddress((void**)&p_aggr, g_aggr);

    cudaFuncSetAttribute(gemm_mma_fused,
                         cudaFuncAttributeMaxDynamicSharedMemorySize, SM_TOTAL);

    prep_weights_kernel<<<3, 256>>>(Wn_w, Wg_w, Wa_w);
    {
        int total_f4 = N * DIM / 4;
        zero_aggr_kernel<<<(total_f4 + 255) / 256, 256>>>(total_f4);
    }
    detect_idx_kernel<<<1, 32>>>((const int*)ei);
    pack_idx_kernel<<<(E + 255) / 256, 256>>>(ei, E);

    int gblocks = (N + 127) / 128;
    // y_n = x@Wn + bn
    gemm_mma_fused<<<gblocks, 256, SM_TOTAL>>>(x, 0, Wn_b, nullptr, p_yn, N, 0);
    // g = x * sigmoid(x@Wa + ba)
    gemm_mma_fused<<<gblocks, 256, SM_TOTAL>>>(x, 2, Wa_b, x, p_ga, N, 1);

    // aggr[row] += g[col]
    {
        long long threads = (long long)E * 32;
        int blocks = (int)((threads + 255) / 256);
        edge_scatter_kernel<<<blocks, 256>>>(E);
    }

    // out = tanh(aggr@Wg + bg + y_n)
    gemm_mma_fused<<<gblocks, 256, SM_TOTAL>>>(p_aggr, 1, Wg_b, p_yn, out, N, 2);
}